// round 16
// baseline (speedup 1.0000x reference)
#include <cuda_runtime.h>
#include <cuda_bf16.h>
#include <math.h>
#include <cstdint>

#define N_NODES 100000
#define D 128
#define EMAX 800000

// Scratch
__device__ float g_deg[2][2][N_NODES];
__device__ float g_y[(size_t)N_NODES * D];
__device__ int g_base[2][N_NODES];
__device__ int g_cursor[2][N_NODES];
__device__ int g_csr[2][EMAX];
__device__ int g_counter[2];

// ---------------- mma tile layout ----------------
#define PITCHE 136
#define PITCH32 68
#define TILEB (128 * PITCHE * 2)   // 34816 bytes per [128][136] bf16 buffer
#define SMA_H 0
#define SMA_L (TILEB)
#define SMB_H (2 * TILEB)
#define SMB_L (3 * TILEB)
#define SMTOT (4 * TILEB)          // 139264

// Prebuilt W^T hi/lo image in EXACT smem layout (BH then BL, contiguous)
__device__ __align__(16) __nv_bfloat16 g_wimg[2][128 * PITCHE];

__device__ __forceinline__ void mma_bf16(float& c0, float& c1, float& c2, float& c3,
                                         uint32_t a0, uint32_t a1, uint32_t a2, uint32_t a3,
                                         uint32_t b0, uint32_t b1) {
    asm volatile(
        "mma.sync.aligned.m16n8k16.row.col.f32.bf16.bf16.f32 "
        "{%0,%1,%2,%3}, {%4,%5,%6,%7}, {%8,%9}, {%0,%1,%2,%3};"
        : "+f"(c0), "+f"(c1), "+f"(c2), "+f"(c3)
        : "r"(a0), "r"(a1), "r"(a2), "r"(a3), "r"(b0), "r"(b1));
}

__device__ __forceinline__ uint32_t pack_bf2(float x, float y) {
    __nv_bfloat162 t = __floats2bfloat162_rn(x, y);
    return *reinterpret_cast<uint32_t*>(&t);
}

// ---------------- W prep (once): Bs[n][k] = W[k][n], split hi/lo, pitch 136 ----------------
__global__ void w_prep_kernel(const float* __restrict__ W) {
    int idx = blockIdx.x * blockDim.x + threadIdx.x;
    if (idx >= D * D) return;
    int k = idx >> 7, n = idx & 127;   // coalesced over n
    float x = W[idx];
    __nv_bfloat16 h = __float2bfloat16(x);
    __nv_bfloat16 l = __float2bfloat16(x - __bfloat162float(h));
    g_wimg[0][n * PITCHE + k] = h;
    g_wimg[1][n * PITCHE + k] = l;
}

// ---------------- degree histograms ----------------
__global__ void degree_kernel(const int* __restrict__ sp, const int* __restrict__ dp,
                              const int* __restrict__ sn, const int* __restrict__ dn, int E) {
    int i = blockIdx.x * blockDim.x + threadIdx.x;
    if (i >= E) return;
    atomicAdd(&g_deg[0][0][sp[i]], 1.0f);
    atomicAdd(&g_deg[0][1][dp[i]], 1.0f);
    atomicAdd(&g_deg[1][0][sn[i]], 1.0f);
    atomicAdd(&g_deg[1][1][dn[i]], 1.0f);
}

// ---------------- CSR base assignment ----------------
__global__ void base_kernel() {
    int set = blockIdx.y;
    int tid = threadIdx.x;
    int v = blockIdx.x * 256 + tid;
    int d = (v < N_NODES) ? (int)g_deg[set][1][v] : 0;

    __shared__ int sh[256];
    sh[tid] = d;
    __syncthreads();
    #pragma unroll
    for (int off = 1; off < 256; off <<= 1) {
        int t = (tid >= off) ? sh[tid - off] : 0;
        __syncthreads();
        sh[tid] += t;
        __syncthreads();
    }
    int excl = sh[tid] - d;

    __shared__ int blockBase;
    if (tid == 255) blockBase = atomicAdd(&g_counter[set], sh[255]);
    __syncthreads();

    if (v < N_NODES) {
        int b = blockBase + excl;
        g_base[set][v] = b;
        g_cursor[set][v] = b;
    }
}

// ---------------- CSR fill ----------------
__global__ void fill_kernel(const int* __restrict__ sp, const int* __restrict__ dp,
                            const int* __restrict__ sn, const int* __restrict__ dn, int E) {
    int i = blockIdx.x * blockDim.x + threadIdx.x;
    if (i >= E) return;
    int p = atomicAdd(&g_cursor[0][dp[i]], 1);
    g_csr[0][p] = sp[i];
    int q = atomicAdd(&g_cursor[1][dn[i]], 1);
    g_csr[1][q] = sn[i];
}

// ---------------- Y = feats @ W via mma.sync bf16 (hi/lo split-3), 512 threads ----------------
__global__ void __launch_bounds__(512, 1) ygemm_mma_kernel(const float* __restrict__ feats) {
    extern __shared__ __align__(16) char smc[];
    uint32_t* AH = reinterpret_cast<uint32_t*>(smc + SMA_H);
    uint32_t* AL = reinterpret_cast<uint32_t*>(smc + SMA_L);
    uint32_t* BH = reinterpret_cast<uint32_t*>(smc + SMB_H);
    uint32_t* BL = reinterpret_cast<uint32_t*>(smc + SMB_L);

    int tid = threadIdx.x;
    int wid = tid >> 5;
    int lane = tid & 31;
    int row0 = blockIdx.x * D;

    // Copy prebuilt W image: BH+BL contiguous = 4352 uint4, conflict-free
    {
        const uint4* src = reinterpret_cast<const uint4*>(&g_wimg[0][0]);
        uint4* dst = reinterpret_cast<uint4*>(smc + SMB_H);
        #pragma unroll
        for (int i = tid; i < 2 * TILEB / 16; i += 512) dst[i] = src[i];
    }
    // Stage A tile: float4 coalesced reads, packed bf16x2 stores
    {
        const float4* Av = reinterpret_cast<const float4*>(feats);
        for (int idx = tid; idx < D * (D / 4); idx += 512) {
            int row = idx >> 5, c4 = idx & 31;
            int grow = row0 + row;
            float4 v = make_float4(0.f, 0.f, 0.f, 0.f);
            if (grow < N_NODES) v = Av[(size_t)grow * (D / 4) + c4];
            __nv_bfloat16 hx = __float2bfloat16(v.x), hy = __float2bfloat16(v.y);
            __nv_bfloat16 hz = __float2bfloat16(v.z), hw = __float2bfloat16(v.w);
            float lx = v.x - __bfloat162float(hx), ly = v.y - __bfloat162float(hy);
            float lz = v.z - __bfloat162float(hz), lw = v.w - __bfloat162float(hw);
            int b32 = row * PITCH32 + c4 * 2;
            __nv_bfloat162 t0 = {hx, hy};
            __nv_bfloat162 t1 = {hz, hw};
            AH[b32] = *reinterpret_cast<uint32_t*>(&t0);
            AH[b32 + 1] = *reinterpret_cast<uint32_t*>(&t1);
            AL[b32] = pack_bf2(lx, ly);
            AL[b32 + 1] = pack_bf2(lz, lw);
        }
    }
    __syncthreads();

    int mwarp = wid >> 2;
    int nwarp = wid & 3;
    int qr = lane >> 2;
    int quad = lane & 3;

    float acc[2][4][4];
    #pragma unroll
    for (int t = 0; t < 2; t++)
        #pragma unroll
        for (int j = 0; j < 4; j++)
            #pragma unroll
            for (int q = 0; q < 4; q++) acc[t][j][q] = 0.0f;

    #pragma unroll
    for (int ks = 0; ks < 8; ks++) {
        int kb = ks * 8 + quad;

        uint32_t ah[2][4], al[2][4];
        #pragma unroll
        for (int t = 0; t < 2; t++) {
            int r = mwarp * 32 + t * 16 + qr;
            int i0 = r * PITCH32 + kb;
            int i1 = (r + 8) * PITCH32 + kb;
            ah[t][0] = AH[i0]; ah[t][1] = AH[i1]; ah[t][2] = AH[i0 + 4]; ah[t][3] = AH[i1 + 4];
            al[t][0] = AL[i0]; al[t][1] = AL[i1]; al[t][2] = AL[i0 + 4]; al[t][3] = AL[i1 + 4];
        }

        #pragma unroll
        for (int j = 0; j < 4; j++) {
            int n = nwarp * 32 + 8 * j + qr;
            int ib = n * PITCH32 + kb;
            uint32_t bh0 = BH[ib], bh1 = BH[ib + 4];
            uint32_t bl0 = BL[ib], bl1 = BL[ib + 4];
            #pragma unroll
            for (int t = 0; t < 2; t++) {
                mma_bf16(acc[t][j][0], acc[t][j][1], acc[t][j][2], acc[t][j][3],
                         ah[t][0], ah[t][1], ah[t][2], ah[t][3], bh0, bh1);
                mma_bf16(acc[t][j][0], acc[t][j][1], acc[t][j][2], acc[t][j][3],
                         ah[t][0], ah[t][1], ah[t][2], ah[t][3], bl0, bl1);
                mma_bf16(acc[t][j][0], acc[t][j][1], acc[t][j][2], acc[t][j][3],
                         al[t][0], al[t][1], al[t][2], al[t][3], bh0, bh1);
            }
        }
    }

    #pragma unroll
    for (int t = 0; t < 2; t++) {
        int ra = row0 + mwarp * 32 + t * 16 + qr;
        int rb = ra + 8;
        #pragma unroll
        for (int j = 0; j < 4; j++) {
            int col = nwarp * 32 + 8 * j + 2 * quad;
            if (ra < N_NODES)
                *reinterpret_cast<float2*>(&g_y[(size_t)ra * D + col]) = make_float2(acc[t][j][0], acc[t][j][1]);
            if (rb < N_NODES)
                *reinterpret_cast<float2*>(&g_y[(size_t)rb * D + col]) = make_float2(acc[t][j][2], acc[t][j][3]);
        }
    }
}

// ---------------- CSR gather: one warp per (set, node), 4-wide SOFTWARE-PIPELINED ----------------
// Next batch's indices + degrees are prefetched while current batch's Y gathers are in flight.
__global__ void gather_kernel(float* __restrict__ out, const float* __restrict__ b,
                              const float* __restrict__ prelu_a) {
    int gw = (blockIdx.x * blockDim.x + threadIdx.x) >> 5;
    int lane = threadIdx.x & 31;
    if (gw >= 2 * N_NODES) return;
    int set = (gw >= N_NODES) ? 1 : 0;
    int v = gw - set * N_NODES;

    int cnt = (int)g_deg[set][1][v];
    int base = g_base[set][v];
    const int* csr = &g_csr[set][0];
    const float* deg_out = &g_deg[set][0][0];
    const float4* Yv = reinterpret_cast<const float4*>(&g_y[0]);

    float ax = 0.f, ay = 0.f, az = 0.f, aw = 0.f;

    int i = 0;
    if (cnt >= 4) {
        // prologue: load batch 0 indices + degrees
        int s0 = csr[base],     s1 = csr[base + 1];
        int s2 = csr[base + 2], s3 = csr[base + 3];
        float d0 = deg_out[s0], d1 = deg_out[s1];
        float d2 = deg_out[s2], d3 = deg_out[s3];

        while (i + 4 <= cnt) {
            // issue Y gathers for current batch
            float4 v0 = Yv[(size_t)s0 * (D / 4) + lane];
            float4 v1 = Yv[(size_t)s1 * (D / 4) + lane];
            float4 v2 = Yv[(size_t)s2 * (D / 4) + lane];
            float4 v3 = Yv[(size_t)s3 * (D / 4) + lane];

            // prefetch next batch indices + degrees while gathers are in flight
            int ni = i + 4;
            int t0 = s0, t1 = s1, t2 = s2, t3 = s3;
            float e0 = d0, e1 = d1, e2 = d2, e3 = d3;
            if (ni + 4 <= cnt) {
                t0 = csr[base + ni];     t1 = csr[base + ni + 1];
                t2 = csr[base + ni + 2]; t3 = csr[base + ni + 3];
                e0 = deg_out[t0]; e1 = deg_out[t1];
                e2 = deg_out[t2]; e3 = deg_out[t3];
            }

            float n0 = rsqrtf(d0), n1 = rsqrtf(d1), n2 = rsqrtf(d2), n3 = rsqrtf(d3);
            ax += v0.x * n0 + v1.x * n1 + v2.x * n2 + v3.x * n3;
            ay += v0.y * n0 + v1.y * n1 + v2.y * n2 + v3.y * n3;
            az += v0.z * n0 + v1.z * n1 + v2.z * n2 + v3.z * n3;
            aw += v0.w * n0 + v1.w * n1 + v2.w * n2 + v3.w * n3;

            s0 = t0; s1 = t1; s2 = t2; s3 = t3;
            d0 = e0; d1 = e1; d2 = e2; d3 = e3;
            i = ni;
        }
    }
    for (; i < cnt; i++) {
        int s = csr[base + i];
        float d = deg_out[s];
        float4 vv = Yv[(size_t)s * (D / 4) + lane];
        float n = rsqrtf(d);
        ax += vv.x * n; ay += vv.y * n; az += vv.z * n; aw += vv.w * n;
    }

    float nd = (cnt > 0) ? rsqrtf((float)cnt) : 0.0f;
    float pa = prelu_a[0];
    float4 bb = reinterpret_cast<const float4*>(b)[lane];

    float h0 = ax * nd + bb.x;
    float h1 = ay * nd + bb.y;
    float h2 = az * nd + bb.z;
    float h3 = aw * nd + bb.w;
    float4 r;
    r.x = (h0 > 0.f) ? h0 : pa * h0;
    r.y = (h1 > 0.f) ? h1 : pa * h1;
    r.z = (h2 > 0.f) ? h2 : pa * h2;
    r.w = (h3 > 0.f) ? h3 : pa * h3;
    reinterpret_cast<float4*>(out)[((size_t)set * N_NODES + v) * (D / 4) + lane] = r;
}

// Lazily-created side stream + events (host objects only).
static cudaStream_t side_stream() {
    static cudaStream_t s = [] { cudaStream_t t; cudaStreamCreate(&t); return t; }();
    return s;
}
static cudaEvent_t ev_fork() {
    static cudaEvent_t e = [] { cudaEvent_t t; cudaEventCreateWithFlags(&t, cudaEventDisableTiming); return t; }();
    return e;
}
static cudaEvent_t ev_join() {
    static cudaEvent_t e = [] { cudaEvent_t t; cudaEventCreateWithFlags(&t, cudaEventDisableTiming); return t; }();
    return e;
}

extern "C" void kernel_launch(void* const* d_in, const int* in_sizes, int n_in,
                              void* d_out, int out_size) {
    const float* feats   = (const float*)d_in[0];
    const float* W       = (const float*)d_in[1];
    const float* b       = (const float*)d_in[2];
    const float* prelu_a = (const float*)d_in[3];
    const int* src_pos   = (const int*)d_in[4];
    const int* dst_pos   = (const int*)d_in[5];
    const int* src_neg   = (const int*)d_in[6];
    const int* dst_neg   = (const int*)d_in[7];
    int E = in_sizes[4];
    float* out = (float*)d_out;

    cudaStream_t s2 = side_stream();
    cudaEvent_t e1 = ev_fork();
    cudaEvent_t e2 = ev_join();

    void* deg_ptr = nullptr;
    void* cnt_ptr = nullptr;
    cudaGetSymbolAddress(&deg_ptr, g_deg);
    cudaGetSymbolAddress(&cnt_ptr, g_counter);

    // Fork: side stream builds degrees + CSR while legacy stream runs w_prep + ygemm.
    cudaEventRecord(e1, 0);
    cudaStreamWaitEvent(s2, e1, 0);

    cudaMemsetAsync(deg_ptr, 0, sizeof(float) * 2 * 2 * N_NODES, s2);
    cudaMemsetAsync(cnt_ptr, 0, sizeof(int) * 2, s2);
    degree_kernel<<<(E + 255) / 256, 256, 0, s2>>>(src_pos, dst_pos, src_neg, dst_neg, E);
    {
        dim3 grid((N_NODES + 255) / 256, 2);
        base_kernel<<<grid, 256, 0, s2>>>();
    }
    fill_kernel<<<(E + 255) / 256, 256, 0, s2>>>(src_pos, dst_pos, src_neg, dst_neg, E);
    cudaEventRecord(e2, s2);

    // Legacy stream: W image prep, then tensor-core ygemm (512 threads).
    w_prep_kernel<<<(D * D + 255) / 256, 256>>>(W);
    cudaFuncSetAttribute(ygemm_mma_kernel, cudaFuncAttributeMaxDynamicSharedMemorySize, SMTOT);
    ygemm_mma_kernel<<<(N_NODES + D - 1) / D, 512, SMTOT>>>(feats);

    // Join, then fused gather.
    cudaStreamWaitEvent(0, e2, 0);

    int gwarps = 2 * N_NODES;
    int gblocks = (gwarps + 7) / 8;
    gather_kernel<<<gblocks, 256>>>(out, b, prelu_a);
}

// round 17
// speedup vs baseline: 1.1643x; 1.1643x over previous
#include <cuda_runtime.h>
#include <cuda_bf16.h>
#include <math.h>
#include <cstdint>

#define N_NODES 100000
#define D 128
#define EMAX 800000

// Scratch. g_deg has a sentinel entry at [set][0][N_NODES] = +inf (rsqrtf -> 0).
__device__ float g_deg[2][2][N_NODES + 1];
__device__ float g_y[((size_t)N_NODES + 1) * D];   // row N_NODES zeroed (sentinel)
__device__ int g_base[2][N_NODES];
__device__ int g_cursor[2][N_NODES];
__device__ int g_csr[2][EMAX + 4];                 // +4 pad for unconditional batch loads
__device__ int g_counter[2];

// ---------------- mma tile layout ----------------
#define PITCHE 136
#define PITCH32 68
#define TILEB (128 * PITCHE * 2)   // 34816 bytes per [128][136] bf16 buffer
#define SMA_H 0
#define SMA_L (TILEB)
#define SMB_H (2 * TILEB)
#define SMB_L (3 * TILEB)
#define SMTOT (4 * TILEB)          // 139264

// Prebuilt W^T hi/lo image in EXACT smem layout (BH then BL, contiguous)
__device__ __align__(16) __nv_bfloat16 g_wimg[2][128 * PITCHE];

__device__ __forceinline__ void mma_bf16(float& c0, float& c1, float& c2, float& c3,
                                         uint32_t a0, uint32_t a1, uint32_t a2, uint32_t a3,
                                         uint32_t b0, uint32_t b1) {
    asm volatile(
        "mma.sync.aligned.m16n8k16.row.col.f32.bf16.bf16.f32 "
        "{%0,%1,%2,%3}, {%4,%5,%6,%7}, {%8,%9}, {%0,%1,%2,%3};"
        : "+f"(c0), "+f"(c1), "+f"(c2), "+f"(c3)
        : "r"(a0), "r"(a1), "r"(a2), "r"(a3), "r"(b0), "r"(b1));
}

__device__ __forceinline__ uint32_t pack_bf2(float x, float y) {
    __nv_bfloat162 t = __floats2bfloat162_rn(x, y);
    return *reinterpret_cast<uint32_t*>(&t);
}

// ---------------- W prep (once): Bs[n][k] = W[k][n], split hi/lo; zero Y sentinel row ----------------
__global__ void w_prep_kernel(const float* __restrict__ W) {
    int idx = blockIdx.x * blockDim.x + threadIdx.x;
    if (idx < D) g_y[(size_t)N_NODES * D + idx] = 0.0f;   // sentinel Y row = 0
    if (idx >= D * D) return;
    int k = idx >> 7, n = idx & 127;   // coalesced over n
    float x = W[idx];
    __nv_bfloat16 h = __float2bfloat16(x);
    __nv_bfloat16 l = __float2bfloat16(x - __bfloat162float(h));
    g_wimg[0][n * PITCHE + k] = h;
    g_wimg[1][n * PITCHE + k] = l;
}

// ---------------- degree histograms (+ sentinel deg = +inf) ----------------
__global__ void degree_kernel(const int* __restrict__ sp, const int* __restrict__ dp,
                              const int* __restrict__ sn, const int* __restrict__ dn, int E) {
    int i = blockIdx.x * blockDim.x + threadIdx.x;
    if (i == 0) {
        float inf = __int_as_float(0x7f800000);
        g_deg[0][0][N_NODES] = inf;
        g_deg[1][0][N_NODES] = inf;
    }
    if (i >= E) return;
    atomicAdd(&g_deg[0][0][sp[i]], 1.0f);
    atomicAdd(&g_deg[0][1][dp[i]], 1.0f);
    atomicAdd(&g_deg[1][0][sn[i]], 1.0f);
    atomicAdd(&g_deg[1][1][dn[i]], 1.0f);
}

// ---------------- CSR base assignment ----------------
__global__ void base_kernel() {
    int set = blockIdx.y;
    int tid = threadIdx.x;
    int v = blockIdx.x * 256 + tid;
    int d = (v < N_NODES) ? (int)g_deg[set][1][v] : 0;

    __shared__ int sh[256];
    sh[tid] = d;
    __syncthreads();
    #pragma unroll
    for (int off = 1; off < 256; off <<= 1) {
        int t = (tid >= off) ? sh[tid - off] : 0;
        __syncthreads();
        sh[tid] += t;
        __syncthreads();
    }
    int excl = sh[tid] - d;

    __shared__ int blockBase;
    if (tid == 255) blockBase = atomicAdd(&g_counter[set], sh[255]);
    __syncthreads();

    if (v < N_NODES) {
        int b = blockBase + excl;
        g_base[set][v] = b;
        g_cursor[set][v] = b;
    }
}

// ---------------- CSR fill ----------------
__global__ void fill_kernel(const int* __restrict__ sp, const int* __restrict__ dp,
                            const int* __restrict__ sn, const int* __restrict__ dn, int E) {
    int i = blockIdx.x * blockDim.x + threadIdx.x;
    if (i >= E) return;
    int p = atomicAdd(&g_cursor[0][dp[i]], 1);
    g_csr[0][p] = sp[i];
    int q = atomicAdd(&g_cursor[1][dn[i]], 1);
    g_csr[1][q] = sn[i];
}

// ---------------- Y = feats @ W via mma.sync bf16 (hi/lo split-3), 512 threads ----------------
__global__ void __launch_bounds__(512, 1) ygemm_mma_kernel(const float* __restrict__ feats) {
    extern __shared__ __align__(16) char smc[];
    uint32_t* AH = reinterpret_cast<uint32_t*>(smc + SMA_H);
    uint32_t* AL = reinterpret_cast<uint32_t*>(smc + SMA_L);
    uint32_t* BH = reinterpret_cast<uint32_t*>(smc + SMB_H);
    uint32_t* BL = reinterpret_cast<uint32_t*>(smc + SMB_L);

    int tid = threadIdx.x;
    int wid = tid >> 5;
    int lane = tid & 31;
    int row0 = blockIdx.x * D;

    // Copy prebuilt W image: BH+BL contiguous = 4352 uint4, conflict-free
    {
        const uint4* src = reinterpret_cast<const uint4*>(&g_wimg[0][0]);
        uint4* dst = reinterpret_cast<uint4*>(smc + SMB_H);
        #pragma unroll
        for (int i = tid; i < 2 * TILEB / 16; i += 512) dst[i] = src[i];
    }
    // Stage A tile: float4 coalesced reads, packed bf16x2 stores
    {
        const float4* Av = reinterpret_cast<const float4*>(feats);
        for (int idx = tid; idx < D * (D / 4); idx += 512) {
            int row = idx >> 5, c4 = idx & 31;
            int grow = row0 + row;
            float4 v = make_float4(0.f, 0.f, 0.f, 0.f);
            if (grow < N_NODES) v = Av[(size_t)grow * (D / 4) + c4];
            __nv_bfloat16 hx = __float2bfloat16(v.x), hy = __float2bfloat16(v.y);
            __nv_bfloat16 hz = __float2bfloat16(v.z), hw = __float2bfloat16(v.w);
            float lx = v.x - __bfloat162float(hx), ly = v.y - __bfloat162float(hy);
            float lz = v.z - __bfloat162float(hz), lw = v.w - __bfloat162float(hw);
            int b32 = row * PITCH32 + c4 * 2;
            __nv_bfloat162 t0 = {hx, hy};
            __nv_bfloat162 t1 = {hz, hw};
            AH[b32] = *reinterpret_cast<uint32_t*>(&t0);
            AH[b32 + 1] = *reinterpret_cast<uint32_t*>(&t1);
            AL[b32] = pack_bf2(lx, ly);
            AL[b32 + 1] = pack_bf2(lz, lw);
        }
    }
    __syncthreads();

    int mwarp = wid >> 2;
    int nwarp = wid & 3;
    int qr = lane >> 2;
    int quad = lane & 3;

    float acc[2][4][4];
    #pragma unroll
    for (int t = 0; t < 2; t++)
        #pragma unroll
        for (int j = 0; j < 4; j++)
            #pragma unroll
            for (int q = 0; q < 4; q++) acc[t][j][q] = 0.0f;

    #pragma unroll
    for (int ks = 0; ks < 8; ks++) {
        int kb = ks * 8 + quad;

        uint32_t ah[2][4], al[2][4];
        #pragma unroll
        for (int t = 0; t < 2; t++) {
            int r = mwarp * 32 + t * 16 + qr;
            int i0 = r * PITCH32 + kb;
            int i1 = (r + 8) * PITCH32 + kb;
            ah[t][0] = AH[i0]; ah[t][1] = AH[i1]; ah[t][2] = AH[i0 + 4]; ah[t][3] = AH[i1 + 4];
            al[t][0] = AL[i0]; al[t][1] = AL[i1]; al[t][2] = AL[i0 + 4]; al[t][3] = AL[i1 + 4];
        }

        #pragma unroll
        for (int j = 0; j < 4; j++) {
            int n = nwarp * 32 + 8 * j + qr;
            int ib = n * PITCH32 + kb;
            uint32_t bh0 = BH[ib], bh1 = BH[ib + 4];
            uint32_t bl0 = BL[ib], bl1 = BL[ib + 4];
            #pragma unroll
            for (int t = 0; t < 2; t++) {
                mma_bf16(acc[t][j][0], acc[t][j][1], acc[t][j][2], acc[t][j][3],
                         ah[t][0], ah[t][1], ah[t][2], ah[t][3], bh0, bh1);
                mma_bf16(acc[t][j][0], acc[t][j][1], acc[t][j][2], acc[t][j][3],
                         ah[t][0], ah[t][1], ah[t][2], ah[t][3], bl0, bl1);
                mma_bf16(acc[t][j][0], acc[t][j][1], acc[t][j][2], acc[t][j][3],
                         al[t][0], al[t][1], al[t][2], al[t][3], bh0, bh1);
            }
        }
    }

    #pragma unroll
    for (int t = 0; t < 2; t++) {
        int ra = row0 + mwarp * 32 + t * 16 + qr;
        int rb = ra + 8;
        #pragma unroll
        for (int j = 0; j < 4; j++) {
            int col = nwarp * 32 + 8 * j + 2 * quad;
            if (ra < N_NODES)
                *reinterpret_cast<float2*>(&g_y[(size_t)ra * D + col]) = make_float2(acc[t][j][0], acc[t][j][1]);
            if (rb < N_NODES)
                *reinterpret_cast<float2*>(&g_y[(size_t)rb * D + col]) = make_float2(acc[t][j][2], acc[t][j][3]);
        }
    }
}

// ---------------- CSR gather: one warp per (set, node), 4-wide, sentinel-padded (NO tail) ----------------
__global__ void gather_kernel(float* __restrict__ out, const float* __restrict__ b,
                              const float* __restrict__ prelu_a) {
    int gw = (blockIdx.x * blockDim.x + threadIdx.x) >> 5;
    int lane = threadIdx.x & 31;
    if (gw >= 2 * N_NODES) return;
    int set = (gw >= N_NODES) ? 1 : 0;
    int v = gw - set * N_NODES;

    int cnt = (int)g_deg[set][1][v];
    int base = g_base[set][v];
    const int* csr = &g_csr[set][0];
    const float* deg_out = &g_deg[set][0][0];
    const float4* Yv = reinterpret_cast<const float4*>(&g_y[0]);

    float ax = 0.f, ay = 0.f, az = 0.f, aw = 0.f;

    int cntp = (cnt + 3) & ~3;   // padded; pad slots map to sentinel N_NODES (deg=inf -> weight 0)
    for (int i = 0; i < cntp; i += 4) {
        int o = base + i;
        // unconditional loads (csr padded by 4), branch-free sentinel select on index
        int r0 = csr[o], r1 = csr[o + 1], r2 = csr[o + 2], r3 = csr[o + 3];
        int s0 = r0;                                  // i+0 < cnt always inside loop
        int s1 = (i + 1 < cnt) ? r1 : N_NODES;
        int s2 = (i + 2 < cnt) ? r2 : N_NODES;
        int s3 = (i + 3 < cnt) ? r3 : N_NODES;
        float d0 = deg_out[s0], d1 = deg_out[s1], d2 = deg_out[s2], d3 = deg_out[s3];
        float4 v0 = Yv[(size_t)s0 * (D / 4) + lane];
        float4 v1 = Yv[(size_t)s1 * (D / 4) + lane];
        float4 v2 = Yv[(size_t)s2 * (D / 4) + lane];
        float4 v3 = Yv[(size_t)s3 * (D / 4) + lane];
        float n0 = rsqrtf(d0), n1 = rsqrtf(d1), n2 = rsqrtf(d2), n3 = rsqrtf(d3);
        ax += v0.x * n0 + v1.x * n1 + v2.x * n2 + v3.x * n3;
        ay += v0.y * n0 + v1.y * n1 + v2.y * n2 + v3.y * n3;
        az += v0.z * n0 + v1.z * n1 + v2.z * n2 + v3.z * n3;
        aw += v0.w * n0 + v1.w * n1 + v2.w * n2 + v3.w * n3;
    }

    float nd = (cnt > 0) ? rsqrtf((float)cnt) : 0.0f;
    float pa = prelu_a[0];
    float4 bb = reinterpret_cast<const float4*>(b)[lane];

    float h0 = ax * nd + bb.x;
    float h1 = ay * nd + bb.y;
    float h2 = az * nd + bb.z;
    float h3 = aw * nd + bb.w;
    float4 r;
    r.x = (h0 > 0.f) ? h0 : pa * h0;
    r.y = (h1 > 0.f) ? h1 : pa * h1;
    r.z = (h2 > 0.f) ? h2 : pa * h2;
    r.w = (h3 > 0.f) ? h3 : pa * h3;
    reinterpret_cast<float4*>(out)[((size_t)set * N_NODES + v) * (D / 4) + lane] = r;
}

// Lazily-created side stream + events (host objects only).
static cudaStream_t side_stream() {
    static cudaStream_t s = [] { cudaStream_t t; cudaStreamCreate(&t); return t; }();
    return s;
}
static cudaEvent_t ev_fork() {
    static cudaEvent_t e = [] { cudaEvent_t t; cudaEventCreateWithFlags(&t, cudaEventDisableTiming); return t; }();
    return e;
}
static cudaEvent_t ev_join() {
    static cudaEvent_t e = [] { cudaEvent_t t; cudaEventCreateWithFlags(&t, cudaEventDisableTiming); return t; }();
    return e;
}

extern "C" void kernel_launch(void* const* d_in, const int* in_sizes, int n_in,
                              void* d_out, int out_size) {
    const float* feats   = (const float*)d_in[0];
    const float* W       = (const float*)d_in[1];
    const float* b       = (const float*)d_in[2];
    const float* prelu_a = (const float*)d_in[3];
    const int* src_pos   = (const int*)d_in[4];
    const int* dst_pos   = (const int*)d_in[5];
    const int* src_neg   = (const int*)d_in[6];
    const int* dst_neg   = (const int*)d_in[7];
    int E = in_sizes[4];
    float* out = (float*)d_out;

    cudaStream_t s2 = side_stream();
    cudaEvent_t e1 = ev_fork();
    cudaEvent_t e2 = ev_join();

    void* deg_ptr = nullptr;
    void* cnt_ptr = nullptr;
    cudaGetSymbolAddress(&deg_ptr, g_deg);
    cudaGetSymbolAddress(&cnt_ptr, g_counter);

    // Fork: side stream builds degrees + CSR while legacy stream runs w_prep + ygemm.
    cudaEventRecord(e1, 0);
    cudaStreamWaitEvent(s2, e1, 0);

    cudaMemsetAsync(deg_ptr, 0, sizeof(float) * 2 * 2 * (N_NODES + 1), s2);
    cudaMemsetAsync(cnt_ptr, 0, sizeof(int) * 2, s2);
    degree_kernel<<<(E + 255) / 256, 256, 0, s2>>>(src_pos, dst_pos, src_neg, dst_neg, E);
    {
        dim3 grid((N_NODES + 255) / 256, 2);
        base_kernel<<<grid, 256, 0, s2>>>();
    }
    fill_kernel<<<(E + 255) / 256, 256, 0, s2>>>(src_pos, dst_pos, src_neg, dst_neg, E);
    cudaEventRecord(e2, s2);

    // Legacy stream: W image prep (+ Y sentinel row zero), then tensor-core ygemm.
    w_prep_kernel<<<(D * D + 255) / 256, 256>>>(W);
    cudaFuncSetAttribute(ygemm_mma_kernel, cudaFuncAttributeMaxDynamicSharedMemorySize, SMTOT);
    ygemm_mma_kernel<<<(N_NODES + D - 1) / D, 512, SMTOT>>>(feats);

    // Join, then fused gather.
    cudaStreamWaitEvent(0, e2, 0);

    int gwarps = 2 * N_NODES;
    int gblocks = (gwarps + 7) / 8;
    gather_kernel<<<gblocks, 256>>>(out, b, prelu_a);
}